// round 14
// baseline (speedup 1.0000x reference)
#include <cuda_runtime.h>
#include <cuda_bf16.h>
#include <math.h>

#define T 2048
#define HID 7168
#define H 16
#define NOPE 128
#define ROPE 64
#define VD 128
#define QLR 1536
#define KVLR 512
#define IH 32
#define ID 128
#define TOPK 512

#define EPS 1e-6f
#define SCALE 0.07216878364870323f    // (192)^-0.5
#define ISCALE 0.08838834764831845f   // 128^-0.5
#define WSCALE 0.17677669529663687f   // 32^-0.5

__device__ __forceinline__ float tf32r(float x) {
    float y;
    asm("cvt.rna.tf32.f32 %0, %1;" : "=f"(y) : "f"(x));
    return y;
}

// ---------------- scratch ----------------
__device__ float g_cos[T * 32];
__device__ float g_sin[T * 32];
__device__ float g_qcn[T * QLR];
__device__ float g_kvn[T * KVLR];
__device__ float g_q[T * (H * (NOPE + ROPE))];
__device__ float g_kv[T * (H * (NOPE + VD))];
__device__ float g_kpe[T * ROPE];
__device__ float g_qidx[T * (IH * ID)];
__device__ float g_kidxraw[T * ID];
__device__ float g_kidx[T * ID];
__device__ float g_widx[T * IH];
__device__ float g_scores[(size_t)T * T];
__device__ int   g_selidx[T * TOPK];
__device__ int   g_selcnt[T];
__device__ float g_obuf[T * (H * VD)];

// ---------------- rope tables ----------------
__global__ void rope_table_kernel(const int* __restrict__ pos) {
    int t = blockIdx.x, i = threadIdx.x;
    float e = (float)(2 * i) / 64.0f;
    float p = (float)pow(10000.0, (double)e);
    float inv = __fdiv_rn(1.0f, p);
    float ang = __fmul_rn((float)pos[t], inv);
    double ad = (double)ang;
    g_cos[t * 32 + i] = (float)cos(ad);
    g_sin[t * 32 + i] = (float)sin(ad);
}

// ---------------- rmsnorm ----------------
__global__ void rmsnorm_kernel(const float* __restrict__ x, const float* __restrict__ w,
                               float* __restrict__ y, int D) {
    int t = blockIdx.x, tid = threadIdx.x;
    const float* xr = x + (size_t)t * D;
    float ss = 0.f;
    for (int i = tid; i < D; i += 256) { float v = xr[i]; ss += v * v; }
    __shared__ float red[256];
    red[tid] = ss; __syncthreads();
    for (int o = 128; o; o >>= 1) { if (tid < o) red[tid] += red[tid + o]; __syncthreads(); }
    float mean = __fdiv_rn(red[0], (float)D);
    float inv = __fdiv_rn(1.0f, __fsqrt_rn(__fadd_rn(mean, EPS)));
    float* yr = y + (size_t)t * D;
    for (int i = tid; i < D; i += 256)
        yr[i] = __fmul_rn(__fmul_rn(xr[i], inv), w[i]);
}

// ---------------- SGEMM (selection path, FROZEN) ----------------
__global__ __launch_bounds__(256) void sgemm_kernel(
    const float* __restrict__ A, const float* __restrict__ B, float* __restrict__ C,
    int M, int N, int K, float scale) {
    __shared__ float As[2][8][128];
    __shared__ float Bs[2][8][128];
    int bm = blockIdx.y * 128, bn = blockIdx.x * 128;
    int tid = threadIdx.x;
    int am = tid >> 1, ak = (tid & 1) * 4;
    int bk = tid >> 5, bn4 = (tid & 31) * 4;
    int tx = tid & 15, ty = tid >> 4;
    float acc[8][8];
#pragma unroll
    for (int i = 0; i < 8; i++)
#pragma unroll
        for (int j = 0; j < 8; j++) acc[i][j] = 0.f;

    const float* Abase = A + (size_t)(bm + am) * K + ak;
    const float* Bbase = B + (size_t)bk * N + bn + bn4;

    {
        float4 av = *(const float4*)(Abase);
        As[0][ak + 0][am] = av.x; As[0][ak + 1][am] = av.y;
        As[0][ak + 2][am] = av.z; As[0][ak + 3][am] = av.w;
        *(float4*)&Bs[0][bk][bn4] = *(const float4*)(Bbase);
    }
    __syncthreads();

    int kIters = K >> 3;
    int cur = 0;
    for (int it = 0; it < kIters; it++) {
        float4 av, bv;
        bool more = (it + 1 < kIters);
        if (more) {
            av = *(const float4*)(Abase + (it + 1) * 8);
            bv = *(const float4*)(Bbase + (size_t)(it + 1) * 8 * N);
        }
#pragma unroll
        for (int kk = 0; kk < 8; kk++) {
            float a[8], b[8];
            *(float4*)(a)     = *(float4*)&As[cur][kk][ty * 4];
            *(float4*)(a + 4) = *(float4*)&As[cur][kk][64 + ty * 4];
            *(float4*)(b)     = *(float4*)&Bs[cur][kk][tx * 4];
            *(float4*)(b + 4) = *(float4*)&Bs[cur][kk][64 + tx * 4];
#pragma unroll
            for (int i = 0; i < 8; i++)
#pragma unroll
                for (int j = 0; j < 8; j++)
                    acc[i][j] = __fmaf_rn(a[i], b[j], acc[i][j]);
        }
        if (more) {
            int nxt = cur ^ 1;
            As[nxt][ak + 0][am] = av.x; As[nxt][ak + 1][am] = av.y;
            As[nxt][ak + 2][am] = av.z; As[nxt][ak + 3][am] = av.w;
            *(float4*)&Bs[nxt][bk][bn4] = bv;
            __syncthreads();
            cur = nxt;
        }
    }
#pragma unroll
    for (int i = 0; i < 8; i++) {
        int m = bm + ((i < 4) ? (ty * 4 + i) : (64 + ty * 4 + i - 4));
#pragma unroll
        for (int jb = 0; jb < 2; jb++) {
            int n = bn + ((jb == 0) ? (tx * 4) : (64 + tx * 4));
            float4 v;
            v.x = __fmul_rn(acc[i][jb * 4 + 0], scale);
            v.y = __fmul_rn(acc[i][jb * 4 + 1], scale);
            v.z = __fmul_rn(acc[i][jb * 4 + 2], scale);
            v.w = __fmul_rn(acc[i][jb * 4 + 3], scale);
            *(float4*)(C + (size_t)m * N + n) = v;
        }
    }
}

// ---------------- 3xTF32 tensor-core GEMM, float2-packed hi/lo fragments ----------------
// C[M,N] = A[M,K] @ B[K,N]. 128x128 tile, k-chunk 16, 8 warps (2x4), warp 64x32.
__global__ __launch_bounds__(256) void mma3_sgemm_kernel(
    const float* __restrict__ A, const float* __restrict__ B, float* __restrict__ C,
    int M, int N, int K) {
    __shared__ float2 Ap[16][132];   // [k][m] {hi,lo}
    __shared__ float2 Bp[16][132];   // [k][n] {hi,lo}
    int bm = blockIdx.y * 128, bn = blockIdx.x * 128;
    int tid = threadIdx.x;
    int wid = tid >> 5, lane = tid & 31;
    int wm = (wid >> 2) * 64;
    int wn = (wid & 3) * 32;

    float c[4][4][4];
#pragma unroll
    for (int i = 0; i < 4; i++)
#pragma unroll
        for (int j = 0; j < 4; j++)
#pragma unroll
            for (int r = 0; r < 4; r++) c[i][j][r] = 0.f;

    int arow = tid >> 1, akk = (tid & 1) * 8;
    int brow = tid >> 4, bnn = (tid & 15) * 8;
    const float* Aload = A + (size_t)(bm + arow) * K + akk;
    const float* Bload = B + (size_t)brow * N + bn + bnn;

    int lq = lane >> 2, lr = lane & 3;

    for (int k0 = 0; k0 < K; k0 += 16) {
        {
            float4 a0 = *(const float4*)(Aload + k0);
            float4 a1 = *(const float4*)(Aload + k0 + 4);
            float av[8] = {a0.x, a0.y, a0.z, a0.w, a1.x, a1.y, a1.z, a1.w};
#pragma unroll
            for (int i = 0; i < 8; i++) {
                float hi = tf32r(av[i]);
                Ap[akk + i][arow] = make_float2(hi, tf32r(__fsub_rn(av[i], hi)));
            }
            float4 b0 = *(const float4*)(Bload + (size_t)k0 * N);
            float4 b1 = *(const float4*)(Bload + (size_t)k0 * N + 4);
            float bv[8] = {b0.x, b0.y, b0.z, b0.w, b1.x, b1.y, b1.z, b1.w};
#pragma unroll
            for (int i = 0; i < 8; i++) {
                float hi = tf32r(bv[i]);
                Bp[brow][bnn + i] = make_float2(hi, tf32r(__fsub_rn(bv[i], hi)));
            }
        }
        __syncthreads();

#pragma unroll
        for (int ks = 0; ks < 16; ks += 8) {
            unsigned bh[4][2], bl[4][2];
#pragma unroll
            for (int j = 0; j < 4; j++) {
                int nn = wn + j * 8 + lq;
                float2 b0 = Bp[ks + lr][nn];
                float2 b1 = Bp[ks + lr + 4][nn];
                bh[j][0] = __float_as_uint(b0.x); bl[j][0] = __float_as_uint(b0.y);
                bh[j][1] = __float_as_uint(b1.x); bl[j][1] = __float_as_uint(b1.y);
            }
#pragma unroll
            for (int i = 0; i < 4; i++) {
                int mm = wm + i * 16 + lq;
                float2 a0 = Ap[ks + lr][mm];
                float2 a1 = Ap[ks + lr][mm + 8];
                float2 a2 = Ap[ks + lr + 4][mm];
                float2 a3 = Ap[ks + lr + 4][mm + 8];
                unsigned ah[4], al[4];
                ah[0] = __float_as_uint(a0.x); al[0] = __float_as_uint(a0.y);
                ah[1] = __float_as_uint(a1.x); al[1] = __float_as_uint(a1.y);
                ah[2] = __float_as_uint(a2.x); al[2] = __float_as_uint(a2.y);
                ah[3] = __float_as_uint(a3.x); al[3] = __float_as_uint(a3.y);
#pragma unroll
                for (int j = 0; j < 4; j++) {
                    float* cc = c[i][j];
                    asm volatile(
                        "mma.sync.aligned.m16n8k8.row.col.f32.tf32.tf32.f32 "
                        "{%0,%1,%2,%3}, {%4,%5,%6,%7}, {%8,%9}, {%0,%1,%2,%3};"
                        : "+f"(cc[0]), "+f"(cc[1]), "+f"(cc[2]), "+f"(cc[3])
                        : "r"(ah[0]), "r"(ah[1]), "r"(ah[2]), "r"(ah[3]),
                          "r"(bh[j][0]), "r"(bh[j][1]));
                    asm volatile(
                        "mma.sync.aligned.m16n8k8.row.col.f32.tf32.tf32.f32 "
                        "{%0,%1,%2,%3}, {%4,%5,%6,%7}, {%8,%9}, {%0,%1,%2,%3};"
                        : "+f"(cc[0]), "+f"(cc[1]), "+f"(cc[2]), "+f"(cc[3])
                        : "r"(ah[0]), "r"(ah[1]), "r"(ah[2]), "r"(ah[3]),
                          "r"(bl[j][0]), "r"(bl[j][1]));
                    asm volatile(
                        "mma.sync.aligned.m16n8k8.row.col.f32.tf32.tf32.f32 "
                        "{%0,%1,%2,%3}, {%4,%5,%6,%7}, {%8,%9}, {%0,%1,%2,%3};"
                        : "+f"(cc[0]), "+f"(cc[1]), "+f"(cc[2]), "+f"(cc[3])
                        : "r"(al[0]), "r"(al[1]), "r"(al[2]), "r"(al[3]),
                          "r"(bh[j][0]), "r"(bh[j][1]));
                }
            }
        }
        __syncthreads();
    }

#pragma unroll
    for (int i = 0; i < 4; i++) {
        int m0 = bm + wm + i * 16 + lq;
#pragma unroll
        for (int j = 0; j < 4; j++) {
            int n0 = bn + wn + j * 8 + lr * 2;
            float2 v0 = make_float2(c[i][j][0], c[i][j][1]);
            float2 v1 = make_float2(c[i][j][2], c[i][j][3]);
            *(float2*)(C + (size_t)m0 * N + n0) = v0;
            *(float2*)(C + (size_t)(m0 + 8) * N + n0) = v1;
        }
    }
}

// ---------------- skinny SGEMM (selection path, FROZEN) ----------------
__global__ __launch_bounds__(256) void skinny_sgemm_kernel(
    const float* __restrict__ A, const float* __restrict__ B, float* __restrict__ C,
    int M, int N, int K, float scale) {
    __shared__ float As[32][33];
    __shared__ float Bs[32][128];
    int tid = threadIdx.x;
    int ncol4 = N >> 2;
    int rows = 256 / ncol4;
    int bm = blockIdx.y * rows;
    int row = tid / ncol4;
    int c4 = tid % ncol4;

    float acc0 = 0.f, acc1 = 0.f, acc2 = 0.f, acc3 = 0.f;
    int totalA = rows * 32;
    int totalf4 = 32 * ncol4;

    for (int k0 = 0; k0 < K; k0 += 32) {
        for (int idx = tid; idx < totalA; idx += 256) {
            int r = idx >> 5, kk = idx & 31;
            As[kk][r] = A[(size_t)(bm + r) * K + k0 + kk];
        }
        for (int idx = tid; idx < totalf4; idx += 256) {
            int kk = idx / ncol4, cc = idx % ncol4;
            *(float4*)&Bs[kk][cc * 4] =
                *(const float4*)(B + (size_t)(k0 + kk) * N + cc * 4);
        }
        __syncthreads();
#pragma unroll
        for (int kk = 0; kk < 32; kk++) {
            float a = As[kk][row];
            float4 b = *(float4*)&Bs[kk][c4 * 4];
            acc0 = __fmaf_rn(a, b.x, acc0);
            acc1 = __fmaf_rn(a, b.y, acc1);
            acc2 = __fmaf_rn(a, b.z, acc2);
            acc3 = __fmaf_rn(a, b.w, acc3);
        }
        __syncthreads();
    }
    float4 v;
    v.x = __fmul_rn(acc0, scale);
    v.y = __fmul_rn(acc1, scale);
    v.z = __fmul_rn(acc2, scale);
    v.w = __fmul_rn(acc3, scale);
    *(float4*)(C + (size_t)(bm + row) * N + c4 * 4) = v;
}

// ---------------- rope kernels ----------------
__global__ void rope_q_kernel() {
    int th = blockIdx.x;
    int t = th / H, h = th % H;
    int i = threadIdx.x;
    float c = g_cos[t * 32 + i], s = g_sin[t * 32 + i];
    float* p = g_q + (size_t)t * 3072 + h * 192 + 128 + 2 * i;
    float xe = p[0], xo = p[1];
    p[0] = __fsub_rn(__fmul_rn(xe, c), __fmul_rn(xo, s));
    p[1] = __fadd_rn(__fmul_rn(xo, c), __fmul_rn(xe, s));
}

__global__ void rope_kpe_kernel(const float* __restrict__ k_pe) {
    int t = blockIdx.x;
    int i = threadIdx.x;
    float c = g_cos[t * 32 + i], s = g_sin[t * 32 + i];
    const float* p = k_pe + (size_t)t * 64 + 2 * i;
    float xe = p[0], xo = p[1];
    g_kpe[t * 64 + 2 * i]     = __fsub_rn(__fmul_rn(xe, c), __fmul_rn(xo, s));
    g_kpe[t * 64 + 2 * i + 1] = __fadd_rn(__fmul_rn(xo, c), __fmul_rn(xe, s));
}

__global__ void rope_qidx_kernel() {
    int tih = blockIdx.x;
    int t = tih / IH, ih = tih % IH;
    int i = threadIdx.x;
    float c = g_cos[t * 32 + i], s = g_sin[t * 32 + i];
    float* p = g_qidx + (size_t)t * 4096 + ih * 128;
    float x1 = p[i], x2 = p[32 + i];
    p[i]      = __fsub_rn(__fmul_rn(x1, c), __fmul_rn(x2, s));
    p[32 + i] = __fadd_rn(__fmul_rn(x2, c), __fmul_rn(x1, s));
}

__global__ void kidx_kernel(const float* __restrict__ gamma, const float* __restrict__ beta) {
    int t = blockIdx.x, tid = threadIdx.x;
    __shared__ float x[128];
    __shared__ float red[128];
    float v = g_kidxraw[(size_t)t * 128 + tid];
    red[tid] = v; __syncthreads();
    for (int o = 64; o; o >>= 1) { if (tid < o) red[tid] += red[tid + o]; __syncthreads(); }
    float mu = __fdiv_rn(red[0], 128.f); __syncthreads();
    float d = __fsub_rn(v, mu);
    red[tid] = __fmul_rn(d, d); __syncthreads();
    for (int o = 64; o; o >>= 1) { if (tid < o) red[tid] += red[tid + o]; __syncthreads(); }
    float var = __fdiv_rn(red[0], 128.f);
    float inv = __fdiv_rn(1.0f, __fsqrt_rn(__fadd_rn(var, EPS)));
    x[tid] = __fadd_rn(__fmul_rn(__fmul_rn(d, inv), gamma[tid]), beta[tid]);
    __syncthreads();
    if (tid < 32) {
        float c = g_cos[t * 32 + tid], s = g_sin[t * 32 + tid];
        float x1 = x[tid], x2 = x[tid + 32];
        g_kidx[(size_t)t * 128 + tid]      = __fsub_rn(__fmul_rn(x1, c), __fmul_rn(x2, s));
        g_kidx[(size_t)t * 128 + tid + 32] = __fadd_rn(__fmul_rn(x2, c), __fmul_rn(x1, s));
    } else if (tid >= 64) {
        g_kidx[(size_t)t * 128 + tid] = x[tid];
    }
}

// ---------------- indexer scores (FROZEN) ----------------
#define SC_SLICES 4
__global__ __launch_bounds__(256) void scores_kernel() {
    int t = (T - 1) - blockIdx.y;
    int slice = blockIdx.x;
    __shared__ float qs[32 * 129];
    __shared__ float ks[32 * 129];
    __shared__ float ws[32];
    __shared__ float lg[32][33];
    int tid = threadIdx.x;
    for (int i = tid; i < 4096; i += 256) {
        int hh = i >> 7, dd = i & 127;
        qs[hh * 129 + dd] = g_qidx[(size_t)t * 4096 + i];
    }
    if (tid < 32) ws[tid] = g_widx[t * 32 + tid];
    int ntile = t / 32 + 1;
    int jl = (tid & 15) * 2;
    int hl = (tid >> 4) * 2;
    for (int jt = slice; jt < ntile; jt += SC_SLICES) {
        int jbase = jt * 32;
        __syncthreads();
        for (int i = tid; i < 4096; i += 256) {
            int jj = i >> 7, dd = i & 127;
            ks[jj * 129 + dd] = g_kidx[(size_t)jbase * 128 + i];
        }
        __syncthreads();
        float a00 = 0.f, a01 = 0.f, a10 = 0.f, a11 = 0.f;
        const float* q0 = &qs[hl * 129];
        const float* q1 = &qs[(hl + 1) * 129];
        const float* k0 = &ks[jl * 129];
        const float* k1 = &ks[(jl + 1) * 129];
#pragma unroll 8
        for (int d = 0; d < 128; d++) {
            float kv0 = k0[d], kv1 = k1[d];
            float qv0 = q0[d], qv1 = q1[d];
            a00 = __fmaf_rn(qv0, kv0, a00); a01 = __fmaf_rn(qv0, kv1, a01);
            a10 = __fmaf_rn(qv1, kv0, a10); a11 = __fmaf_rn(qv1, kv1, a11);
        }
        lg[hl][jl]         = fmaxf(__fmul_rn(a00, ISCALE), 0.f);
        lg[hl][jl + 1]     = fmaxf(__fmul_rn(a01, ISCALE), 0.f);
        lg[hl + 1][jl]     = fmaxf(__fmul_rn(a10, ISCALE), 0.f);
        lg[hl + 1][jl + 1] = fmaxf(__fmul_rn(a11, ISCALE), 0.f);
        __syncthreads();
        if (tid < 32) {
            int j = jbase + tid;
            float s = 0.f;
#pragma unroll
            for (int h = 0; h < 32; h++)
                s = __fmaf_rn(ws[h], lg[h][tid], s);
            g_scores[(size_t)t * T + j] = (j <= t) ? s : -INFINITY;
        }
    }
    for (int j = ntile * 32 + slice * 256 + tid; j < T; j += SC_SLICES * 256)
        g_scores[(size_t)t * T + j] = -INFINITY;
}

// ---------------- top-512 (FROZEN semantics) ----------------
__global__ __launch_bounds__(1024) void topk_kernel() {
    int t = blockIdx.x, tid = threadIdx.x;
    if (t <= TOPK - 2) {
        int cnt = t + 1;
        if (tid == 0) g_selcnt[t] = cnt;
        for (int k = tid; k < cnt; k += 1024) g_selidx[t * TOPK + k] = k;
        return;
    }
    __shared__ unsigned long long keys[2048];
    for (int i = tid; i < 2048; i += 1024) {
        float s = g_scores[(size_t)t * T + i];
        unsigned u = __float_as_uint(s);
        u = (u & 0x80000000u) ? ~u : (u | 0x80000000u);
        keys[i] = ((unsigned long long)u << 32) | (unsigned)(2047 - i);
    }
    __syncthreads();
    for (int k = 2; k <= 2048; k <<= 1) {
        for (int j = k >> 1; j > 0; j >>= 1) {
            for (int i = tid; i < 2048; i += 1024) {
                int ixj = i ^ j;
                if (ixj > i) {
                    unsigned long long a = keys[i], b = keys[ixj];
                    bool desc = ((i & k) == 0);
                    if (desc ? (a < b) : (a > b)) { keys[i] = b; keys[ixj] = a; }
                }
            }
            __syncthreads();
        }
    }
    if (tid == 0) g_selcnt[t] = TOPK;
    if (tid < TOPK) {
        g_selidx[t * TOPK + tid] = 2047 - (int)(keys[tid] & 0xFFFFFFFFu);
    }
}

// ---------------- attention: R11-proven TB=4 row-grouped version ----------------
#define TB 4
__global__ __launch_bounds__(128) void attn_kernel() {
    int h = blockIdx.x;
    int grp = (T / TB - 1) - blockIdx.y;
    int base = grp * TB;
    int tid = threadIdx.x, wid = tid >> 5, lane = tid & 31;
    int tmax = base + TB - 1;

    __shared__ float qn[TB][128];
    __shared__ float qp[TB][64];
    __shared__ unsigned mbits[TB][64];
    __shared__ float plog[TB][2048];
    __shared__ float outacc[4][TB][128];

#pragma unroll
    for (int b = 0; b < TB; b++) {
        int t = base + b;
        qn[b][tid] = g_q[(size_t)t * 3072 + h * 192 + tid];
        if (tid < 64) qp[b][tid] = g_q[(size_t)t * 3072 + h * 192 + 128 + tid];
    }
    for (int i = tid; i < TB * 64; i += 128) ((unsigned*)mbits)[i] = 0;
#pragma unroll
    for (int b = 0; b < TB; b++)
        for (int j = tid; j <= tmax; j += 128) plog[b][j] = -INFINITY;
    __syncthreads();

#pragma unroll
    for (int b = 0; b < TB; b++) {
        int t = base + b;
        int cnt = g_selcnt[t];
        for (int k = tid; k < cnt; k += 128) {
            int j = g_selidx[t * TOPK + k];
            atomicOr(&mbits[b][j >> 5], 1u << (j & 31));
        }
    }
    __syncthreads();

    for (int j = wid; j <= tmax; j += 4) {
        unsigned sel4 = 0;
#pragma unroll
        for (int b = 0; b < TB; b++)
            sel4 |= ((mbits[b][j >> 5] >> (j & 31)) & 1u) << b;
        if (!sel4) continue;
        const float* kn = g_kv + (size_t)j * 4096 + h * 256;
        const float* kp = g_kpe + (size_t)j * 64;
        float k0 = kn[lane], k1 = kn[lane + 32], k2 = kn[lane + 64], k3 = kn[lane + 96];
        float p0 = kp[lane], p1 = kp[lane + 32];
        float s[TB];
#pragma unroll
        for (int b = 0; b < TB; b++) {
            float sb = qn[b][lane] * k0;
            sb = __fmaf_rn(qn[b][lane + 32], k1, sb);
            sb = __fmaf_rn(qn[b][lane + 64], k2, sb);
            sb = __fmaf_rn(qn[b][lane + 96], k3, sb);
            sb = __fmaf_rn(qp[b][lane], p0, sb);
            sb = __fmaf_rn(qp[b][lane + 32], p1, sb);
            s[b] = sb;
        }
#pragma unroll
        for (int o = 16; o; o >>= 1) {
#pragma unroll
            for (int b = 0; b < TB; b++)
                s[b] += __shfl_xor_sync(0xffffffffu, s[b], o);
        }
        if (lane == 0) {
#pragma unroll
            for (int b = 0; b < TB; b++)
                if ((sel4 >> b) & 1) plog[b][j] = s[b] * SCALE;
        }
    }
    __syncthreads();

    {
        int b = wid;
        float m = -INFINITY;
        for (int j = lane; j <= tmax; j += 32) m = fmaxf(m, plog[b][j]);
#pragma unroll
        for (int o = 16; o; o >>= 1) m = fmaxf(m, __shfl_xor_sync(0xffffffffu, m, o));
        float sum = 0.f;
        for (int j = lane; j <= tmax; j += 32) {
            float p = __expf(plog[b][j] - m);
            plog[b][j] = p;
            sum += p;
        }
#pragma unroll
        for (int o = 16; o; o >>= 1) sum += __shfl_xor_sync(0xffffffffu, sum, o);
        float inv = __fdiv_rn(1.0f, sum);
        for (int j = lane; j <= tmax; j += 32) plog[b][j] *= inv;
    }
    __syncthreads();

    float a[TB][4];
#pragma unroll
    for (int b = 0; b < TB; b++)
#pragma unroll
        for (int i = 0; i < 4; i++) a[b][i] = 0.f;
    for (int j = wid; j <= tmax; j += 4) {
        unsigned any = 0;
#pragma unroll
        for (int b = 0; b < TB; b++) any |= mbits[b][j >> 5] & (1u << (j & 31));
        if (!any) continue;
        const float* v = g_kv + (size_t)j * 4096 + h * 256 + 128;
        float v0 = v[lane], v1 = v[lane + 32], v2 = v[lane + 64], v3 = v[lane + 96];
#pragma unroll
        for (int b = 0; b < TB; b++) {
            float p = plog[b][j];
            a[b][0] = __fmaf_rn(p, v0, a[b][0]);
            a[b][1] = __fmaf_rn(p, v1, a[b][1]);
            a[b][2] = __fmaf_rn(p, v2, a[b][2]);
            a[b][3] = __fmaf_rn(p, v3, a[b][3]);
        }
    }
#pragma unroll
    for (int b = 0; b < TB; b++) {
        outacc[wid][b][lane]      = a[b][0];
        outacc[wid][b][lane + 32] = a[b][1];
        outacc[wid][b][lane + 64] = a[b][2];
        outacc[wid][b][lane + 96] = a[b][3];
    }
    __syncthreads();
#pragma unroll
    for (int b = 0; b < TB; b++) {
        float sv = (outacc[0][b][tid] + outacc[1][b][tid])
                 + (outacc[2][b][tid] + outacc[3][b][tid]);
        g_obuf[(size_t)(base + b) * 2048 + h * 128 + tid] = sv;
    }
}

// ---------------- launch ----------------
extern "C" void kernel_launch(void* const* d_in, const int* in_sizes, int n_in,
                              void* d_out, int out_size) {
    const int*   positions = (const int*)d_in[0];
    const float* hidden    = (const float*)d_in[1];
    const float* q_c       = (const float*)d_in[2];
    const float* kv_c      = (const float*)d_in[3];
    const float* k_pe      = (const float*)d_in[4];
    const float* q_a_ln_w  = (const float*)d_in[5];
    const float* kv_a_ln_w = (const float*)d_in[6];
    const float* Wq_b      = (const float*)d_in[7];
    const float* Wkv_b     = (const float*)d_in[8];
    const float* Wo        = (const float*)d_in[9];
    const float* Wiq       = (const float*)d_in[10];
    const float* Wik       = (const float*)d_in[11];
    const float* ik_gamma  = (const float*)d_in[12];
    const float* ik_beta   = (const float*)d_in[13];
    const float* Ww        = (const float*)d_in[14];
    float* out = (float*)d_out;

    float* p_qcn;     cudaGetSymbolAddress((void**)&p_qcn, g_qcn);
    float* p_kvn;     cudaGetSymbolAddress((void**)&p_kvn, g_kvn);
    float* p_q;       cudaGetSymbolAddress((void**)&p_q, g_q);
    float* p_kv;      cudaGetSymbolAddress((void**)&p_kv, g_kv);
    float* p_qidx;    cudaGetSymbolAddress((void**)&p_qidx, g_qidx);
    float* p_kidxraw; cudaGetSymbolAddress((void**)&p_kidxraw, g_kidxraw);
    float* p_widx;    cudaGetSymbolAddress((void**)&p_widx, g_widx);
    float* p_obuf;    cudaGetSymbolAddress((void**)&p_obuf, g_obuf);

    rope_table_kernel<<<T, 32>>>(positions);
    rmsnorm_kernel<<<T, 256>>>(q_c, q_a_ln_w, p_qcn, QLR);
    rmsnorm_kernel<<<T, 256>>>(kv_c, kv_a_ln_w, p_kvn, KVLR);

    // continuous-path GEMMs -> 3xTF32 tensor cores (float2-packed fragments)
    mma3_sgemm_kernel<<<dim3(3072 / 128, T / 128), 256>>>(p_qcn, Wq_b, p_q, T, 3072, QLR);
    mma3_sgemm_kernel<<<dim3(4096 / 128, T / 128), 256>>>(p_kvn, Wkv_b, p_kv, T, 4096, KVLR);

    // selection-critical path -> frozen FMA-chain kernels
    sgemm_kernel<<<dim3(4096 / 128, T / 128), 256>>>(p_qcn, Wiq, p_qidx, T, 4096, QLR, 1.f);
    skinny_sgemm_kernel<<<dim3(1, T / 8), 256>>>(hidden, Wik, p_kidxraw, T, 128, HID, 1.f);
    skinny_sgemm_kernel<<<dim3(1, T / 32), 256>>>(hidden, Ww, p_widx, T, 32, HID, WSCALE);

    rope_q_kernel<<<T * H, 32>>>();
    rope_kpe_kernel<<<T, 32>>>(k_pe);
    rope_qidx_kernel<<<T * IH, 32>>>();
    kidx_kernel<<<T, 128>>>(ik_gamma, ik_beta);

    scores_kernel<<<dim3(SC_SLICES, T), 256>>>();
    topk_kernel<<<T, 1024>>>();
    attn_kernel<<<dim3(H, T / TB), 128>>>();

    mma3_sgemm_kernel<<<dim3(HID / 128, T / 128), 256>>>(p_obuf, Wo, out, T, HID, 2048);
}

// round 15
// speedup vs baseline: 1.1137x; 1.1137x over previous
#include <cuda_runtime.h>
#include <cuda_bf16.h>
#include <math.h>

#define T 2048
#define HID 7168
#define H 16
#define NOPE 128
#define ROPE 64
#define VD 128
#define QLR 1536
#define KVLR 512
#define IH 32
#define ID 128
#define TOPK 512

#define EPS 1e-6f
#define SCALE 0.07216878364870323f    // (192)^-0.5
#define ISCALE 0.08838834764831845f   // 128^-0.5
#define WSCALE 0.17677669529663687f   // 32^-0.5

// ---------------- scratch (device globals; no cudaMalloc allowed) ----------------
__device__ float g_cos[T * 32];
__device__ float g_sin[T * 32];
__device__ float g_qcn[T * QLR];
__device__ float g_kvn[T * KVLR];
__device__ float g_q[T * (H * (NOPE + ROPE))];      // T x 3072
__device__ float g_kv[T * (H * (NOPE + VD))];       // T x 4096
__device__ float g_kpe[T * ROPE];
__device__ float g_qidx[T * (IH * ID)];             // T x 4096
__device__ float g_kidxraw[T * ID];
__device__ float g_kidx[T * ID];
__device__ float g_widx[T * IH];
__device__ float g_scores[(size_t)T * T];
__device__ int   g_selidx[T * TOPK];
__device__ int   g_selcnt[T];
__device__ float g_obuf[T * (H * VD)];              // T x 2048

// ---------------- rope tables (correctly-rounded fp32 chain via double) ----------------
__global__ void rope_table_kernel(const int* __restrict__ pos) {
    int t = blockIdx.x, i = threadIdx.x;
    float e = (float)(2 * i) / 64.0f;
    float p = (float)pow(10000.0, (double)e);
    float inv = __fdiv_rn(1.0f, p);
    float ang = __fmul_rn((float)pos[t], inv);
    double ad = (double)ang;
    g_cos[t * 32 + i] = (float)cos(ad);
    g_sin[t * 32 + i] = (float)sin(ad);
}

// ---------------- rmsnorm (strict fp32 scale path) ----------------
__global__ void rmsnorm_kernel(const float* __restrict__ x, const float* __restrict__ w,
                               float* __restrict__ y, int D) {
    int t = blockIdx.x, tid = threadIdx.x;
    const float* xr = x + (size_t)t * D;
    float ss = 0.f;
    for (int i = tid; i < D; i += 256) { float v = xr[i]; ss += v * v; }
    __shared__ float red[256];
    red[tid] = ss; __syncthreads();
    for (int o = 128; o; o >>= 1) { if (tid < o) red[tid] += red[tid + o]; __syncthreads(); }
    float mean = __fdiv_rn(red[0], (float)D);
    float inv = __fdiv_rn(1.0f, __fsqrt_rn(__fadd_rn(mean, EPS)));
    float* yr = y + (size_t)t * D;
    for (int i = tid; i < D; i += 256)
        yr[i] = __fmul_rn(__fmul_rn(xr[i], inv), w[i]);
}

// ---------------- SGEMM: double-buffered, k-chunk 8 (proven), k-ascending FMA chain ----------------
__global__ __launch_bounds__(256) void sgemm_kernel(
    const float* __restrict__ A, const float* __restrict__ B, float* __restrict__ C,
    int M, int N, int K, float scale) {
    __shared__ float As[2][8][128];
    __shared__ float Bs[2][8][128];
    int bm = blockIdx.y * 128, bn = blockIdx.x * 128;
    int tid = threadIdx.x;
    int am = tid >> 1, ak = (tid & 1) * 4;
    int bk = tid >> 5, bn4 = (tid & 31) * 4;
    int tx = tid & 15, ty = tid >> 4;
    float acc[8][8];
#pragma unroll
    for (int i = 0; i < 8; i++)
#pragma unroll
        for (int j = 0; j < 8; j++) acc[i][j] = 0.f;

    const float* Abase = A + (size_t)(bm + am) * K + ak;
    const float* Bbase = B + (size_t)bk * N + bn + bn4;

    {
        float4 av = *(const float4*)(Abase);
        As[0][ak + 0][am] = av.x; As[0][ak + 1][am] = av.y;
        As[0][ak + 2][am] = av.z; As[0][ak + 3][am] = av.w;
        *(float4*)&Bs[0][bk][bn4] = *(const float4*)(Bbase);
    }
    __syncthreads();

    int kIters = K >> 3;
    int cur = 0;
    for (int it = 0; it < kIters; it++) {
        float4 av, bv;
        bool more = (it + 1 < kIters);
        if (more) {
            av = *(const float4*)(Abase + (it + 1) * 8);
            bv = *(const float4*)(Bbase + (size_t)(it + 1) * 8 * N);
        }
#pragma unroll
        for (int kk = 0; kk < 8; kk++) {
            float a[8], b[8];
            *(float4*)(a)     = *(float4*)&As[cur][kk][ty * 4];
            *(float4*)(a + 4) = *(float4*)&As[cur][kk][64 + ty * 4];
            *(float4*)(b)     = *(float4*)&Bs[cur][kk][tx * 4];
            *(float4*)(b + 4) = *(float4*)&Bs[cur][kk][64 + tx * 4];
#pragma unroll
            for (int i = 0; i < 8; i++)
#pragma unroll
                for (int j = 0; j < 8; j++)
                    acc[i][j] = __fmaf_rn(a[i], b[j], acc[i][j]);
        }
        if (more) {
            int nxt = cur ^ 1;
            As[nxt][ak + 0][am] = av.x; As[nxt][ak + 1][am] = av.y;
            As[nxt][ak + 2][am] = av.z; As[nxt][ak + 3][am] = av.w;
            *(float4*)&Bs[nxt][bk][bn4] = bv;
            __syncthreads();
            cur = nxt;
        }
    }
#pragma unroll
    for (int i = 0; i < 8; i++) {
        int m = bm + ((i < 4) ? (ty * 4 + i) : (64 + ty * 4 + i - 4));
#pragma unroll
        for (int jb = 0; jb < 2; jb++) {
            int n = bn + ((jb == 0) ? (tx * 4) : (64 + tx * 4));
            float4 v;
            v.x = __fmul_rn(acc[i][jb * 4 + 0], scale);
            v.y = __fmul_rn(acc[i][jb * 4 + 1], scale);
            v.z = __fmul_rn(acc[i][jb * 4 + 2], scale);
            v.w = __fmul_rn(acc[i][jb * 4 + 3], scale);
            *(float4*)(C + (size_t)m * N + n) = v;
        }
    }
}

// ---------------- skinny SGEMM (N<=128): rows_per_block = 256/(N/4) ----------------
__global__ __launch_bounds__(256) void skinny_sgemm_kernel(
    const float* __restrict__ A, const float* __restrict__ B, float* __restrict__ C,
    int M, int N, int K, float scale) {
    __shared__ float As[32][33];
    __shared__ float Bs[32][128];
    int tid = threadIdx.x;
    int ncol4 = N >> 2;
    int rows = 256 / ncol4;
    int bm = blockIdx.y * rows;
    int row = tid / ncol4;
    int c4 = tid % ncol4;

    float acc0 = 0.f, acc1 = 0.f, acc2 = 0.f, acc3 = 0.f;
    int totalA = rows * 32;
    int totalf4 = 32 * ncol4;

    for (int k0 = 0; k0 < K; k0 += 32) {
        for (int idx = tid; idx < totalA; idx += 256) {
            int r = idx >> 5, kk = idx & 31;
            As[kk][r] = A[(size_t)(bm + r) * K + k0 + kk];
        }
        for (int idx = tid; idx < totalf4; idx += 256) {
            int kk = idx / ncol4, cc = idx % ncol4;
            *(float4*)&Bs[kk][cc * 4] =
                *(const float4*)(B + (size_t)(k0 + kk) * N + cc * 4);
        }
        __syncthreads();
#pragma unroll
        for (int kk = 0; kk < 32; kk++) {
            float a = As[kk][row];
            float4 b = *(float4*)&Bs[kk][c4 * 4];
            acc0 = __fmaf_rn(a, b.x, acc0);
            acc1 = __fmaf_rn(a, b.y, acc1);
            acc2 = __fmaf_rn(a, b.z, acc2);
            acc3 = __fmaf_rn(a, b.w, acc3);
        }
        __syncthreads();
    }
    float4 v;
    v.x = __fmul_rn(acc0, scale);
    v.y = __fmul_rn(acc1, scale);
    v.z = __fmul_rn(acc2, scale);
    v.w = __fmul_rn(acc3, scale);
    *(float4*)(C + (size_t)(bm + row) * N + c4 * 4) = v;
}

// ---------------- rope (interleaved) on q_pe ----------------
__global__ void rope_q_kernel() {
    int th = blockIdx.x;
    int t = th / H, h = th % H;
    int i = threadIdx.x;
    float c = g_cos[t * 32 + i], s = g_sin[t * 32 + i];
    float* p = g_q + (size_t)t * 3072 + h * 192 + 128 + 2 * i;
    float xe = p[0], xo = p[1];
    p[0] = __fsub_rn(__fmul_rn(xe, c), __fmul_rn(xo, s));
    p[1] = __fadd_rn(__fmul_rn(xo, c), __fmul_rn(xe, s));
}

// ---------------- rope (interleaved) on k_pe -> g_kpe ----------------
__global__ void rope_kpe_kernel(const float* __restrict__ k_pe) {
    int t = blockIdx.x;
    int i = threadIdx.x;
    float c = g_cos[t * 32 + i], s = g_sin[t * 32 + i];
    const float* p = k_pe + (size_t)t * 64 + 2 * i;
    float xe = p[0], xo = p[1];
    g_kpe[t * 64 + 2 * i]     = __fsub_rn(__fmul_rn(xe, c), __fmul_rn(xo, s));
    g_kpe[t * 64 + 2 * i + 1] = __fadd_rn(__fmul_rn(xo, c), __fmul_rn(xe, s));
}

// ---------------- rope (neox) on q_idx first 64 dims ----------------
__global__ void rope_qidx_kernel() {
    int tih = blockIdx.x;
    int t = tih / IH, ih = tih % IH;
    int i = threadIdx.x;
    float c = g_cos[t * 32 + i], s = g_sin[t * 32 + i];
    float* p = g_qidx + (size_t)t * 4096 + ih * 128;
    float x1 = p[i], x2 = p[32 + i];
    p[i]      = __fsub_rn(__fmul_rn(x1, c), __fmul_rn(x2, s));
    p[32 + i] = __fadd_rn(__fmul_rn(x2, c), __fmul_rn(x1, s));
}

// ---------------- k_idx: layernorm + neox rope ----------------
__global__ void kidx_kernel(const float* __restrict__ gamma, const float* __restrict__ beta) {
    int t = blockIdx.x, tid = threadIdx.x;
    __shared__ float x[128];
    __shared__ float red[128];
    float v = g_kidxraw[(size_t)t * 128 + tid];
    red[tid] = v; __syncthreads();
    for (int o = 64; o; o >>= 1) { if (tid < o) red[tid] += red[tid + o]; __syncthreads(); }
    float mu = __fdiv_rn(red[0], 128.f); __syncthreads();
    float d = __fsub_rn(v, mu);
    red[tid] = __fmul_rn(d, d); __syncthreads();
    for (int o = 64; o; o >>= 1) { if (tid < o) red[tid] += red[tid + o]; __syncthreads(); }
    float var = __fdiv_rn(red[0], 128.f);
    float inv = __fdiv_rn(1.0f, __fsqrt_rn(__fadd_rn(var, EPS)));
    x[tid] = __fadd_rn(__fmul_rn(__fmul_rn(d, inv), gamma[tid]), beta[tid]);
    __syncthreads();
    if (tid < 32) {
        float c = g_cos[t * 32 + tid], s = g_sin[t * 32 + tid];
        float x1 = x[tid], x2 = x[tid + 32];
        g_kidx[(size_t)t * 128 + tid]      = __fsub_rn(__fmul_rn(x1, c), __fmul_rn(x2, s));
        g_kidx[(size_t)t * 128 + tid + 32] = __fadd_rn(__fmul_rn(x2, c), __fmul_rn(x1, s));
    } else if (tid >= 64) {
        g_kidx[(size_t)t * 128 + tid] = x[tid];
    }
}

// ---------------- indexer scores: grid (4 slices, T rows), longest rows first ----------------
#define SC_SLICES 4
__global__ __launch_bounds__(256) void scores_kernel() {
    int t = (T - 1) - blockIdx.y;
    int slice = blockIdx.x;
    __shared__ float qs[32 * 129];
    __shared__ float ks[32 * 129];
    __shared__ float ws[32];
    __shared__ float lg[32][33];
    int tid = threadIdx.x;
    for (int i = tid; i < 4096; i += 256) {
        int hh = i >> 7, dd = i & 127;
        qs[hh * 129 + dd] = g_qidx[(size_t)t * 4096 + i];
    }
    if (tid < 32) ws[tid] = g_widx[t * 32 + tid];
    int ntile = t / 32 + 1;
    int jl = (tid & 15) * 2;
    int hl = (tid >> 4) * 2;
    for (int jt = slice; jt < ntile; jt += SC_SLICES) {
        int jbase = jt * 32;
        __syncthreads();
        for (int i = tid; i < 4096; i += 256) {
            int jj = i >> 7, dd = i & 127;
            ks[jj * 129 + dd] = g_kidx[(size_t)jbase * 128 + i];
        }
        __syncthreads();
        float a00 = 0.f, a01 = 0.f, a10 = 0.f, a11 = 0.f;
        const float* q0 = &qs[hl * 129];
        const float* q1 = &qs[(hl + 1) * 129];
        const float* k0 = &ks[jl * 129];
        const float* k1 = &ks[(jl + 1) * 129];
#pragma unroll 8
        for (int d = 0; d < 128; d++) {
            float kv0 = k0[d], kv1 = k1[d];
            float qv0 = q0[d], qv1 = q1[d];
            a00 = __fmaf_rn(qv0, kv0, a00); a01 = __fmaf_rn(qv0, kv1, a01);
            a10 = __fmaf_rn(qv1, kv0, a10); a11 = __fmaf_rn(qv1, kv1, a11);
        }
        lg[hl][jl]         = fmaxf(__fmul_rn(a00, ISCALE), 0.f);
        lg[hl][jl + 1]     = fmaxf(__fmul_rn(a01, ISCALE), 0.f);
        lg[hl + 1][jl]     = fmaxf(__fmul_rn(a10, ISCALE), 0.f);
        lg[hl + 1][jl + 1] = fmaxf(__fmul_rn(a11, ISCALE), 0.f);
        __syncthreads();
        if (tid < 32) {
            int j = jbase + tid;
            float s = 0.f;
#pragma unroll
            for (int h = 0; h < 32; h++)
                s = __fmaf_rn(ws[h], lg[h][tid], s);
            g_scores[(size_t)t * T + j] = (j <= t) ? s : -INFINITY;
        }
    }
    for (int j = ntile * 32 + slice * 256 + tid; j < T; j += SC_SLICES * 256)
        g_scores[(size_t)t * T + j] = -INFINITY;
}

// ---------------- per-row top-512: quick path for t<=510, bitonic sort otherwise ----------------
__global__ __launch_bounds__(1024) void topk_kernel() {
    int t = blockIdx.x, tid = threadIdx.x;
    if (t <= TOPK - 2) {
        int cnt = t + 1;
        if (tid == 0) g_selcnt[t] = cnt;
        for (int k = tid; k < cnt; k += 1024) g_selidx[t * TOPK + k] = k;
        return;
    }
    __shared__ unsigned long long keys[2048];
    for (int i = tid; i < 2048; i += 1024) {
        float s = g_scores[(size_t)t * T + i];
        unsigned u = __float_as_uint(s);
        u = (u & 0x80000000u) ? ~u : (u | 0x80000000u);
        keys[i] = ((unsigned long long)u << 32) | (unsigned)(2047 - i);
    }
    __syncthreads();
    for (int k = 2; k <= 2048; k <<= 1) {
        for (int j = k >> 1; j > 0; j >>= 1) {
            for (int i = tid; i < 2048; i += 1024) {
                int ixj = i ^ j;
                if (ixj > i) {
                    unsigned long long a = keys[i], b = keys[ixj];
                    bool desc = ((i & k) == 0);
                    if (desc ? (a < b) : (a > b)) { keys[i] = b; keys[ixj] = a; }
                }
            }
            __syncthreads();
        }
    }
    if (tid == 0) g_selcnt[t] = TOPK;
    if (tid < TOPK) {
        g_selidx[t * TOPK + tid] = 2047 - (int)(keys[tid] & 0xFFFFFFFFu);
    }
}

// ---------------- attention: R11-proven TB=4 row-grouped version ----------------
#define TB 4
__global__ __launch_bounds__(128) void attn_kernel() {
    int h = blockIdx.x;
    int grp = (T / TB - 1) - blockIdx.y;
    int base = grp * TB;
    int tid = threadIdx.x, wid = tid >> 5, lane = tid & 31;
    int tmax = base + TB - 1;

    __shared__ float qn[TB][128];
    __shared__ float qp[TB][64];
    __shared__ unsigned mbits[TB][64];
    __shared__ float plog[TB][2048];
    __shared__ float outacc[4][TB][128];

#pragma unroll
    for (int b = 0; b < TB; b++) {
        int t = base + b;
        qn[b][tid] = g_q[(size_t)t * 3072 + h * 192 + tid];
        if (tid < 64) qp[b][tid] = g_q[(size_t)t * 3072 + h * 192 + 128 + tid];
    }
    for (int i = tid; i < TB * 64; i += 128) ((unsigned*)mbits)[i] = 0;
#pragma unroll
    for (int b = 0; b < TB; b++)
        for (int j = tid; j <= tmax; j += 128) plog[b][j] = -INFINITY;
    __syncthreads();

#pragma unroll
    for (int b = 0; b < TB; b++) {
        int t = base + b;
        int cnt = g_selcnt[t];
        for (int k = tid; k < cnt; k += 128) {
            int j = g_selidx[t * TOPK + k];
            atomicOr(&mbits[b][j >> 5], 1u << (j & 31));
        }
    }
    __syncthreads();

    for (int j = wid; j <= tmax; j += 4) {
        unsigned sel4 = 0;
#pragma unroll
        for (int b = 0; b < TB; b++)
            sel4 |= ((mbits[b][j >> 5] >> (j & 31)) & 1u) << b;
        if (!sel4) continue;
        const float* kn = g_kv + (size_t)j * 4096 + h * 256;
        const float* kp = g_kpe + (size_t)j * 64;
        float k0 = kn[lane], k1 = kn[lane + 32], k2 = kn[lane + 64], k3 = kn[lane + 96];
        float p0 = kp[lane], p1 = kp[lane + 32];
        float s[TB];
#pragma unroll
        for (int b = 0; b < TB; b++) {
            float sb = qn[b][lane] * k0;
            sb = __fmaf_rn(qn[b][lane + 32], k1, sb);
            sb = __fmaf_rn(qn[b][lane + 64], k2, sb);
            sb = __fmaf_rn(qn[b][lane + 96], k3, sb);
            sb = __fmaf_rn(qp[b][lane], p0, sb);
            sb = __fmaf_rn(qp[b][lane + 32], p1, sb);
            s[b] = sb;
        }
#pragma unroll
        for (int o = 16; o; o >>= 1) {
#pragma unroll
            for (int b = 0; b < TB; b++)
                s[b] += __shfl_xor_sync(0xffffffffu, s[b], o);
        }
        if (lane == 0) {
#pragma unroll
            for (int b = 0; b < TB; b++)
                if ((sel4 >> b) & 1) plog[b][j] = s[b] * SCALE;
        }
    }
    __syncthreads();

    {
        int b = wid;
        float m = -INFINITY;
        for (int j = lane; j <= tmax; j += 32) m = fmaxf(m, plog[b][j]);
#pragma unroll
        for (int o = 16; o; o >>= 1) m = fmaxf(m, __shfl_xor_sync(0xffffffffu, m, o));
        float sum = 0.f;
        for (int j = lane; j <= tmax; j += 32) {
            float p = __expf(plog[b][j] - m);
            plog[b][j] = p;
            sum += p;
        }
#pragma unroll
        for (int o = 16; o; o >>= 1) sum += __shfl_xor_sync(0xffffffffu, sum, o);
        float inv = __fdiv_rn(1.0f, sum);
        for (int j = lane; j <= tmax; j += 32) plog[b][j] *= inv;
    }
    __syncthreads();

    float a[TB][4];
#pragma unroll
    for (int b = 0; b < TB; b++)
#pragma unroll
        for (int i = 0; i < 4; i++) a[b][i] = 0.f;
    for (int j = wid; j <= tmax; j += 4) {
        unsigned any = 0;
#pragma unroll
        for (int b = 0; b < TB; b++) any |= mbits[b][j >> 5] & (1u << (j & 31));
        if (!any) continue;
        const float* v = g_kv + (size_t)j * 4096 + h * 256 + 128;
        float v0 = v[lane], v1 = v[lane + 32], v2 = v[lane + 64], v3 = v[lane + 96];
#pragma unroll
        for (int b = 0; b < TB; b++) {
            float p = plog[b][j];
            a[b][0] = __fmaf_rn(p, v0, a[b][0]);
            a[b][1] = __fmaf_rn(p, v1, a[b][1]);
            a[b][2] = __fmaf_rn(p, v2, a[b][2]);
            a[b][3] = __fmaf_rn(p, v3, a[b][3]);
        }
    }
#pragma unroll
    for (int b = 0; b < TB; b++) {
        outacc[wid][b][lane]      = a[b][0];
        outacc[wid][b][lane + 32] = a[b][1];
        outacc[wid][b][lane + 64] = a[b][2];
        outacc[wid][b][lane + 96] = a[b][3];
    }
    __syncthreads();
#pragma unroll
    for (int b = 0; b < TB; b++) {
        float sv = (outacc[0][b][tid] + outacc[1][b][tid])
                 + (outacc[2][b][tid] + outacc[3][b][tid]);
        g_obuf[(size_t)(base + b) * 2048 + h * 128 + tid] = sv;
    }
}

// ---------------- launch: two-stream fork/join (graph-capture compatible) ----------------
extern "C" void kernel_launch(void* const* d_in, const int* in_sizes, int n_in,
                              void* d_out, int out_size) {
    const int*   positions = (const int*)d_in[0];
    const float* hidden    = (const float*)d_in[1];
    const float* q_c       = (const float*)d_in[2];
    const float* kv_c      = (const float*)d_in[3];
    const float* k_pe      = (const float*)d_in[4];
    const float* q_a_ln_w  = (const float*)d_in[5];
    const float* kv_a_ln_w = (const float*)d_in[6];
    const float* Wq_b      = (const float*)d_in[7];
    const float* Wkv_b     = (const float*)d_in[8];
    const float* Wo        = (const float*)d_in[9];
    const float* Wiq       = (const float*)d_in[10];
    const float* Wik       = (const float*)d_in[11];
    const float* ik_gamma  = (const float*)d_in[12];
    const float* ik_beta   = (const float*)d_in[13];
    const float* Ww        = (const float*)d_in[14];
    float* out = (float*)d_out;

    float* p_qcn;     cudaGetSymbolAddress((void**)&p_qcn, g_qcn);
    float* p_kvn;     cudaGetSymbolAddress((void**)&p_kvn, g_kvn);
    float* p_q;       cudaGetSymbolAddress((void**)&p_q, g_q);
    float* p_kv;      cudaGetSymbolAddress((void**)&p_kv, g_kv);
    float* p_qidx;    cudaGetSymbolAddress((void**)&p_qidx, g_qidx);
    float* p_kidxraw; cudaGetSymbolAddress((void**)&p_kidxraw, g_kidxraw);
    float* p_widx;    cudaGetSymbolAddress((void**)&p_widx, g_widx);
    float* p_obuf;    cudaGetSymbolAddress((void**)&p_obuf, g_obuf);

    // one-time stream/event creation (outside any capture: first call is the
    // correctness run). Same ops are enqueued on every call -> deterministic.
    static cudaStream_t s1 = nullptr;
    static cudaEvent_t eFork = nullptr, eSel = nullptr, eAttn = nullptr;
    if (s1 == nullptr) {
        cudaStreamCreateWithFlags(&s1, cudaStreamNonBlocking);
        cudaEventCreateWithFlags(&eFork, cudaEventDisableTiming);
        cudaEventCreateWithFlags(&eSel, cudaEventDisableTiming);
        cudaEventCreateWithFlags(&eAttn, cudaEventDisableTiming);
    }
    cudaStream_t s0 = 0;   // origin (captured) stream

    // --- stream0: shared prerequisites ---
    rope_table_kernel<<<T, 32, 0, s0>>>(positions);
    rmsnorm_kernel<<<T, 256, 0, s0>>>(q_c, q_a_ln_w, p_qcn, QLR);
    cudaEventRecord(eFork, s0);
    cudaStreamWaitEvent(s1, eFork, 0);

    // --- side stream s1: selection inputs needed by scores, then attn inputs ---
    skinny_sgemm_kernel<<<dim3(1, T / 8), 256, 0, s1>>>(hidden, Wik, p_kidxraw, T, 128, HID, 1.f);
    skinny_sgemm_kernel<<<dim3(1, T / 32), 256, 0, s1>>>(hidden, Ww, p_widx, T, 32, HID, WSCALE);
    kidx_kernel<<<T, 128, 0, s1>>>(ik_gamma, ik_beta);
    cudaEventRecord(eSel, s1);
    rmsnorm_kernel<<<T, 256, 0, s1>>>(kv_c, kv_a_ln_w, p_kvn, KVLR);
    sgemm_kernel<<<dim3(4096 / 128, T / 128), 256, 0, s1>>>(p_kvn, Wkv_b, p_kv, T, 4096, KVLR, 1.f);
    rope_kpe_kernel<<<T, 32, 0, s1>>>(k_pe);
    sgemm_kernel<<<dim3(3072 / 128, T / 128), 256, 0, s1>>>(p_qcn, Wq_b, p_q, T, 3072, QLR, 1.f);
    rope_q_kernel<<<T * H, 32, 0, s1>>>();
    cudaEventRecord(eAttn, s1);

    // --- stream0: selection-critical chain ---
    sgemm_kernel<<<dim3(4096 / 128, T / 128), 256, 0, s0>>>(p_qcn, Wiq, p_qidx, T, 4096, QLR, 1.f);
    rope_qidx_kernel<<<T * IH, 32, 0, s0>>>();
    cudaStreamWaitEvent(s0, eSel, 0);
    scores_kernel<<<dim3(SC_SLICES, T), 256, 0, s0>>>();
    topk_kernel<<<T, 1024, 0, s0>>>();
    cudaStreamWaitEvent(s0, eAttn, 0);
    attn_kernel<<<dim3(H, T / TB), 128, 0, s0>>>();
    sgemm_kernel<<<dim3(HID / 128, T / 128), 256, 0, s0>>>(p_obuf, Wo, out, T, HID, 2048, 1.f);
}